// round 1
// baseline (speedup 1.0000x reference)
#include <cuda_runtime.h>

// Problem constants
#define BB   4
#define HH   8
#define LQ   512
#define NBLK 32
#define NTOK 128
#define DH   64
#define QT   64
#define THREADS 256

#define SS_STRIDE 129            // 128 + 1 pad (scalar access, bank spread)
// smem: Qs 1024 f4 | Ks 2048 f4 | Vs 2048 f4 | Ss 64*129 f | sAttn 2048 f
#define SMEM_FLOATS ((1024 + 2048 + 2048) * 4 + 64 * SS_STRIDE + 2048)
#define SMEM_BYTES  (SMEM_FLOATS * 4)

#define OUT_ELEMS  (BB * LQ * HH * DH)          // 1,048,576
#define ATTN_ELEMS (BB * HH * LQ * NBLK * NTOK) // 67,108,864

__device__ __forceinline__ unsigned long long pack2(float x, float y) {
    unsigned long long r;
    asm("mov.b64 %0, {%1,%2};" : "=l"(r) : "f"(x), "f"(y));
    return r;
}
__device__ __forceinline__ float2 unpack2(unsigned long long v) {
    float2 r;
    asm("mov.b64 {%0,%1}, %2;" : "=f"(r.x), "=f"(r.y) : "l"(v));
    return r;
}
// packed dual-FMA: d.lo += a.lo*b.lo ; d.hi += a.hi*b.hi
__device__ __forceinline__ void ffma2(unsigned long long& d,
                                      unsigned long long a,
                                      unsigned long long b) {
    asm("fma.rn.f32x2 %0, %1, %2, %0;" : "+l"(d) : "l"(a), "l"(b));
}

__global__ __launch_bounds__(THREADS)
void attn_sentnorm_kernel(const float* __restrict__ qg,
                          const float* __restrict__ kg,
                          const float* __restrict__ vg,
                          const float* __restrict__ ag,
                          float* __restrict__ out,
                          float* __restrict__ attnw,
                          int write_attn) {
    extern __shared__ __align__(16) float smem[];
    float4* Qs = (float4*)smem;          // [64 rows][16 f4] swizzled
    float4* Ks = Qs + 1024;              // [128 rows][16 f4] swizzled
    float4* Vs = Ks + 2048;              // [128 rows][16 f4] swizzled
    float*  Ss = (float*)(Vs + 2048);    // [64][129] weights W
    float*  sA = Ss + 64 * SS_STRIDE;    // [64][32] attn_s tile

    const int tid = threadIdx.x;
    const int bx  = blockIdx.x;
    const int qt  = bx & 7;
    const int h   = (bx >> 3) & 7;
    const int b   = bx >> 6;
    const int l0  = qt * QT;

    // ---- load Q tile (scale 1/sqrt(64) folded in) + attn_s tile ----
    {
        const float4* qg4 = (const float4*)(qg + ((size_t)((b * HH + h) * LQ + l0)) * DH);
#pragma unroll
        for (int i = 0; i < 4; i++) {
            int idx = tid + i * THREADS;
            int row = idx >> 4, f = idx & 15;
            float4 vq = qg4[idx];
            vq.x *= 0.125f; vq.y *= 0.125f; vq.z *= 0.125f; vq.w *= 0.125f;
            Qs[row * 16 + (f ^ (row & 15))] = vq;
        }
        const float4* ag4 = (const float4*)(ag + ((size_t)((b * HH + h) * LQ + l0)) * NBLK);
        float4* sA4 = (float4*)sA;
#pragma unroll
        for (int i = 0; i < 2; i++) sA4[tid + i * THREADS] = ag4[tid + i * THREADS];
    }

    // GEMM1 thread tiling: 16x16 grid; ty -> 4 q-rows, tx -> 8 t-cols (t = tx + 16c)
    const int tx = tid & 15, ty = tid >> 4;
    const int r0 = ty * 4;
    // GEMM2 thread tiling: 32x8 grid; ty2 -> 2 q-rows, tx2 -> 8 d-cols
    const int tx2 = tid & 7, ty2 = tid >> 3;

    unsigned long long oacc[2][4];  // out accumulators (f32x2 over d-pairs)
#pragma unroll
    for (int r = 0; r < 2; r++)
#pragma unroll
        for (int j = 0; j < 4; j++) oacc[r][j] = 0ULL;

    const size_t kvbase0 = ((size_t)(b * NBLK) * HH + h) * (NTOK * DH);
    const size_t awrow0  = ((size_t)((b * HH + h) * LQ + l0)) * ((size_t)NBLK * NTOK);

    for (int nb = 0; nb < NBLK; ++nb) {
        __syncthreads();  // prev GEMM2 done with Vs/Ss
        // ---- load K,V block (swizzled) ----
        const float4* kg4 = (const float4*)(kg + kvbase0 + (size_t)nb * (HH * NTOK * DH));
        const float4* vg4 = (const float4*)(vg + kvbase0 + (size_t)nb * (HH * NTOK * DH));
#pragma unroll
        for (int i = 0; i < 8; i++) {
            int idx = tid + i * THREADS;
            int t = idx >> 4, f = idx & 15;
            int sidx = t * 16 + (f ^ (t & 15));
            Ks[sidx] = kg4[idx];
            Vs[sidx] = vg4[idx];
        }
        __syncthreads();

        // ---- GEMM1: S[4][8] = Qtile @ K^T (f32x2 over d-pairs) ----
        unsigned long long acc[4][8];
#pragma unroll
        for (int r = 0; r < 4; r++)
#pragma unroll
            for (int c = 0; c < 8; c++) acc[r][c] = 0ULL;

#pragma unroll 4
        for (int d4 = 0; d4 < 16; ++d4) {
            ulonglong2 qv[4];
#pragma unroll
            for (int r = 0; r < 4; r++)
                qv[r] = *reinterpret_cast<const ulonglong2*>(
                    &Qs[(r0 + r) * 16 + (d4 ^ ((r0 + r) & 15))]);
            ulonglong2 kv[8];
#pragma unroll
            for (int c = 0; c < 8; c++)
                kv[c] = *reinterpret_cast<const ulonglong2*>(
                    &Ks[(tx + 16 * c) * 16 + (d4 ^ tx)]);
#pragma unroll
            for (int r = 0; r < 4; r++)
#pragma unroll
                for (int c = 0; c < 8; c++) {
                    ffma2(acc[r][c], qv[r].x, kv[c].x);
                    ffma2(acc[r][c], qv[r].y, kv[c].y);
                }
        }

        // ---- fused softmax epilogue ----
        float ev[4][8];
        float sums[4];
#pragma unroll
        for (int r = 0; r < 4; r++) {
            float s_ = 0.f;
#pragma unroll
            for (int c = 0; c < 8; c++) {
                float2 p = unpack2(acc[r][c]);
                float e = __expf(p.x + p.y);
                ev[r][c] = e;
                s_ += e;
            }
            sums[r] = s_;
        }
        // reduce across the 16 lanes owning each row (one half-warp)
#pragma unroll
        for (int off = 1; off < 16; off <<= 1)
#pragma unroll
            for (int r = 0; r < 4; r++)
                sums[r] += __shfl_xor_sync(0xffffffffu, sums[r], off);

        float coef[4];
#pragma unroll
        for (int r = 0; r < 4; r++)
            coef[r] = __fdividef(sA[(r0 + r) * NBLK + nb], sums[r]);

#pragma unroll
        for (int r = 0; r < 4; r++) {
            float* ssrow = Ss + (r0 + r) * SS_STRIDE;
            float* awrow = attnw + awrow0 + (size_t)(r0 + r) * (NBLK * NTOK) + (size_t)nb * NTOK;
#pragma unroll
            for (int c = 0; c < 8; c++) {
                float w = ev[r][c] * coef[r];
                int t = tx + 16 * c;
                ssrow[t] = w;
                if (write_attn) awrow[t] = w;
            }
        }
        __syncthreads();

        // ---- GEMM2: out += W @ V (f32x2 over d-pairs, coef already folded) ----
        const float* w0p = Ss + (2 * ty2) * SS_STRIDE;
        const float* w1p = w0p + SS_STRIDE;
#pragma unroll 2
        for (int t = 0; t < NTOK; ++t) {
            unsigned long long w02 = pack2(w0p[t], w0p[t]);
            unsigned long long w12 = pack2(w1p[t], w1p[t]);
            int sw = t & 15;
            ulonglong2 v0 = *reinterpret_cast<const ulonglong2*>(
                &Vs[t * 16 + ((2 * tx2) ^ sw)]);
            ulonglong2 v1 = *reinterpret_cast<const ulonglong2*>(
                &Vs[t * 16 + ((2 * tx2 + 1) ^ sw)]);
            ffma2(oacc[0][0], w02, v0.x); ffma2(oacc[0][1], w02, v0.y);
            ffma2(oacc[0][2], w02, v1.x); ffma2(oacc[0][3], w02, v1.y);
            ffma2(oacc[1][0], w12, v0.x); ffma2(oacc[1][1], w12, v0.y);
            ffma2(oacc[1][2], w12, v1.x); ffma2(oacc[1][3], w12, v1.y);
        }
    }

    // ---- store out [b][l][h*64+d] ----
#pragma unroll
    for (int r = 0; r < 2; r++) {
        float* orow = out + ((size_t)(b * LQ + l0 + 2 * ty2 + r)) * (HH * DH) + h * DH + tx2 * 8;
#pragma unroll
        for (int j = 0; j < 4; j++) {
            float2 p = unpack2(oacc[r][j]);
            *reinterpret_cast<float2*>(orow + j * 2) = p;
        }
    }
}

extern "C" void kernel_launch(void* const* d_in, const int* in_sizes, int n_in,
                              void* d_out, int out_size) {
    const float* q = (const float*)d_in[0];
    const float* k = (const float*)d_in[1];
    const float* v = (const float*)d_in[2];
    const float* a = (const float*)d_in[3];
    float* out = (float*)d_out;

    int write_attn = (out_size >= OUT_ELEMS + ATTN_ELEMS) ? 1 : 0;
    float* attnw = out + OUT_ELEMS;

    cudaFuncSetAttribute(attn_sentnorm_kernel,
                         cudaFuncAttributeMaxDynamicSharedMemorySize, SMEM_BYTES);

    dim3 grid(BB * HH * (LQ / QT));  // 256
    attn_sentnorm_kernel<<<grid, THREADS, SMEM_BYTES>>>(q, k, v, a, out, attnw, write_attn);
}

// round 5
// speedup vs baseline: 3.8358x; 3.8358x over previous
#include <cuda_runtime.h>
#include <cuda_bf16.h>
#include <cstdint>

#define BB 4
#define HH 8
#define LQ 512
#define NBLK 32
#define NTOK 128
#define DH 64
#define MT 128
#define THREADS 256

#define OUT_ELEMS  (BB * LQ * HH * DH)
#define ATTN_ELEMS ((size_t)BB * HH * LQ * NBLK * NTOK)

// bf16 row strides (elements): 64+8 and 128+8 -> 144B / 272B rows, bank-shift 4
#define QSTR 72
#define WSTR 136

// smem byte offsets
#define OFF_QH 0
#define OFF_QL (OFF_QH + 128 * QSTR * 2)     // 18432 each
#define OFF_KH (OFF_QL + 128 * QSTR * 2)
#define OFF_KL (OFF_KH + 128 * QSTR * 2)
#define OFF_VH (OFF_KL + 128 * QSTR * 2)
#define OFF_VL (OFF_VH + 128 * QSTR * 2)
#define OFF_WH (OFF_VL + 128 * QSTR * 2)     // 34816 each
#define OFF_WL (OFF_WH + 128 * WSTR * 2)
#define OFF_AS (OFF_WL + 128 * WSTR * 2)     // attn_s 128x32 f32
#define OFF_RS (OFF_AS + 128 * 32 * 4)       // rowsum 128x4 f32
#define SMEM_BYTES (OFF_RS + 128 * 4 * 4)    // 198656

typedef unsigned long long ull;

__device__ __forceinline__ uint32_t s2u(const void* p) {
    uint32_t a;
    asm("{ .reg .u64 t; cvta.to.shared.u64 t, %1; cvt.u32.u64 %0, t; }" : "=r"(a) : "l"(p));
    return a;
}
__device__ __forceinline__ ull pack2(float x, float y) {
    ull r; asm("mov.b64 %0, {%1,%2};" : "=l"(r) : "f"(x), "f"(y)); return r;
}
__device__ __forceinline__ void unpack2(ull v, float& x, float& y) {
    asm("mov.b64 {%0,%1}, %2;" : "=f"(x), "=f"(y) : "l"(v));
}
__device__ __forceinline__ ull add2(ull a, ull b) {
    ull d; asm("add.rn.f32x2 %0, %1, %2;" : "=l"(d) : "l"(a), "l"(b)); return d;
}
__device__ __forceinline__ ull mul2(ull a, ull b) {
    ull d; asm("mul.rn.f32x2 %0, %1, %2;" : "=l"(d) : "l"(a), "l"(b)); return d;
}
__device__ __forceinline__ ull fma2(ull a, ull b, ull c) {
    ull d; asm("fma.rn.f32x2 %0, %1, %2, %3;" : "=l"(d) : "l"(a), "l"(b), "l"(c)); return d;
}

__device__ __forceinline__ void ldsm4(uint32_t* r, uint32_t a) {
    asm volatile("ldmatrix.sync.aligned.m8n8.x4.shared.b16 {%0,%1,%2,%3}, [%4];"
                 : "=r"(r[0]), "=r"(r[1]), "=r"(r[2]), "=r"(r[3]) : "r"(a));
}
__device__ __forceinline__ void ldsm2(uint32_t* r, uint32_t a) {
    asm volatile("ldmatrix.sync.aligned.m8n8.x2.shared.b16 {%0,%1}, [%2];"
                 : "=r"(r[0]), "=r"(r[1]) : "r"(a));
}
__device__ __forceinline__ void ldsm2t(uint32_t* r, uint32_t a) {
    asm volatile("ldmatrix.sync.aligned.m8n8.x2.trans.shared.b16 {%0,%1}, [%2];"
                 : "=r"(r[0]), "=r"(r[1]) : "r"(a));
}
__device__ __forceinline__ void mma16816(float* c, const uint32_t* a, const uint32_t* b) {
    asm volatile(
        "mma.sync.aligned.m16n8k16.row.col.f32.bf16.bf16.f32 "
        "{%0,%1,%2,%3}, {%4,%5,%6,%7}, {%8,%9}, {%0,%1,%2,%3};"
        : "+f"(c[0]), "+f"(c[1]), "+f"(c[2]), "+f"(c[3])
        : "r"(a[0]), "r"(a[1]), "r"(a[2]), "r"(a[3]), "r"(b[0]), "r"(b[1]));
}

// split one fp32 tile row-chunk (float4) into bf16 hi/lo, store 8B each
__device__ __forceinline__ void split_store(float4 v, char* base_hi, char* base_lo) {
    __nv_bfloat162 h0 = __floats2bfloat162_rn(v.x, v.y);
    __nv_bfloat162 h1 = __floats2bfloat162_rn(v.z, v.w);
    float lx = v.x - __bfloat162float(h0.x);
    float ly = v.y - __bfloat162float(h0.y);
    float lz = v.z - __bfloat162float(h1.x);
    float lw = v.w - __bfloat162float(h1.y);
    __nv_bfloat162 e0 = __floats2bfloat162_rn(lx, ly);
    __nv_bfloat162 e1 = __floats2bfloat162_rn(lz, lw);
    uint2 hh; hh.x = *(uint32_t*)&h0; hh.y = *(uint32_t*)&h1;
    uint2 ll; ll.x = *(uint32_t*)&e0; ll.y = *(uint32_t*)&e1;
    *(uint2*)base_hi = hh;
    *(uint2*)base_lo = ll;
}

__global__ __launch_bounds__(THREADS, 1)
void attn_mma_kernel(const float* __restrict__ qg, const float* __restrict__ kg,
                     const float* __restrict__ vg, const float* __restrict__ ag,
                     float* __restrict__ out, float* __restrict__ attnw, int write_attn) {
    extern __shared__ __align__(16) char sm[];
    const uint32_t sb = s2u(sm);
    const int tid = threadIdx.x, lane = tid & 31, wid = tid >> 5;
    const int bx = blockIdx.x;
    const int qt = bx & 3, hd = (bx >> 2) & 7, b = bx >> 5;
    const int l0 = qt * MT;

    // ---- Q load + split (scale = 1/8 * log2e folded: S ends up in log2 domain) ----
    {
        const float SC = 0.125f * 1.4426950408889634f;
        const float4* qg4 = (const float4*)(qg + (size_t)((b * HH + hd) * LQ + l0) * DH);
#pragma unroll
        for (int i = 0; i < 8; i++) {
            int idx = tid + i * THREADS;
            int row = idx >> 4, c4 = idx & 15;
            float4 v = qg4[idx];
            v.x *= SC; v.y *= SC; v.z *= SC; v.w *= SC;
            char* base = sm + row * (QSTR * 2) + c4 * 8;
            split_store(v, base + OFF_QH, base + OFF_QL);
        }
        const float4* ag4 = (const float4*)(ag + (size_t)((b * HH + hd) * LQ + l0) * NBLK);
        float4* as4 = (float4*)(sm + OFF_AS);
#pragma unroll
        for (int i = 0; i < 4; i++) as4[tid + i * THREADS] = ag4[tid + i * THREADS];
    }
    __syncthreads();

    const int wn = wid & 3, wm = wid >> 2;
    const int g = lane >> 2, qd = lane & 3;

    // ldmatrix base addresses
    const uint32_t aQ = sb + OFF_QH +
        (uint32_t)(((wm * 64 + (lane & 15)) * QSTR + (lane >> 4) * 8) * 2);
    const uint32_t bK = sb + OFF_KH +
        (uint32_t)(((wn * 32 + (lane & 7)) * QSTR + ((lane >> 3) & 1) * 8) * 2);
    const uint32_t aW = sb + OFF_WH +
        (uint32_t)(((wid * 16 + (lane & 15)) * WSTR + (lane >> 4) * 8) * 2);
    const uint32_t bV = sb + OFF_VH + (uint32_t)(((lane & 15) * QSTR) * 2);

    float* rs = (float*)(sm + OFF_RS);
    float* sAs = (float*)(sm + OFF_AS);

    float acc2[8][4];
#pragma unroll
    for (int i = 0; i < 8; i++)
#pragma unroll
        for (int j = 0; j < 4; j++) acc2[i][j] = 0.f;

    // exp2 constants (packed)
    const ull MAGIC2 = 0x4B4000004B400000ULL;   // 12582912.0f x2
    const ull NMAGIC2 = 0xCB400000CB400000ULL;  // -12582912.0f x2
    const ull NEG1_2 = 0xBF800000BF800000ULL;
    const ull ONE2 = 0x3F8000003F800000ULL;
    const ull C5 = pack2(0.0013333558f, 0.0013333558f);
    const ull C4 = pack2(0.0096181291f, 0.0096181291f);
    const ull C3 = pack2(0.0555041087f, 0.0555041087f);
    const ull C2 = pack2(0.2402265070f, 0.2402265070f);
    const ull C1 = pack2(0.6931471806f, 0.6931471806f);

    for (int nb = 0; nb < NBLK; nb++) {
        __syncthreads();  // (a) prev GEMM2 done with V/W before overwrite of K/V
        {
            const size_t kvoff = ((size_t)((b * NBLK + nb) * HH + hd)) * (NTOK * DH);
            const float4* kg4 = (const float4*)(kg + kvoff);
            const float4* vg4 = (const float4*)(vg + kvoff);
#pragma unroll
            for (int i = 0; i < 8; i++) {
                int idx = tid + i * THREADS;
                int row = idx >> 4, c4 = idx & 15;
                char* base = sm + row * (QSTR * 2) + c4 * 8;
                split_store(kg4[idx], base + OFF_KH, base + OFF_KL);
                split_store(vg4[idx], base + OFF_VH, base + OFF_VL);
            }
        }
        __syncthreads();  // (b)

        // ---- GEMM1: S(warp m64n32) = Q @ K^T, 3 bf16 products ----
        float acc[4][4][4];
#pragma unroll
        for (int mi = 0; mi < 4; mi++)
#pragma unroll
            for (int ni = 0; ni < 4; ni++)
#pragma unroll
                for (int j = 0; j < 4; j++) acc[mi][ni][j] = 0.f;

#pragma unroll
        for (int ks = 0; ks < 4; ks++) {
            uint32_t Ah[4][4], Al[4][4], Bh[4][2], Bl[4][2];
#pragma unroll
            for (int mi = 0; mi < 4; mi++) {
                ldsm4(Ah[mi], aQ + mi * (16 * QSTR * 2) + ks * 32);
                ldsm4(Al[mi], aQ + (OFF_QL - OFF_QH) + mi * (16 * QSTR * 2) + ks * 32);
            }
#pragma unroll
            for (int ni = 0; ni < 4; ni++) {
                ldsm2(Bh[ni], bK + ni * (8 * QSTR * 2) + ks * 32);
                ldsm2(Bl[ni], bK + (OFF_KL - OFF_KH) + ni * (8 * QSTR * 2) + ks * 32);
            }
#pragma unroll
            for (int mi = 0; mi < 4; mi++)
#pragma unroll
                for (int ni = 0; ni < 4; ni++) {
                    mma16816(acc[mi][ni], Ah[mi], Bh[ni]);
                    mma16816(acc[mi][ni], Ah[mi], Bl[ni]);
                    mma16816(acc[mi][ni], Al[mi], Bh[ni]);
                }
        }

        // ---- softmax: e = 2^S (S already in log2 domain), rowsums ----
#pragma unroll
        for (int mi = 0; mi < 4; mi++)
#pragma unroll
            for (int h2 = 0; h2 < 2; h2++) {
                ull s2 = 0ULL;
#pragma unroll
                for (int ni = 0; ni < 4; ni++) {
                    ull y2 = pack2(acc[mi][ni][2 * h2], acc[mi][ni][2 * h2 + 1]);
                    ull t2 = add2(y2, MAGIC2);
                    ull u2 = add2(t2, NMAGIC2);
                    ull f2 = fma2(u2, NEG1_2, y2);       // f = y - round(y)
                    ull p2 = fma2(C5, f2, C4);
                    p2 = fma2(p2, f2, C3);
                    p2 = fma2(p2, f2, C2);
                    p2 = fma2(p2, f2, C1);
                    p2 = fma2(p2, f2, ONE2);
                    uint32_t tlo = (uint32_t)t2, thi = (uint32_t)(t2 >> 32);
                    uint32_t plo = (uint32_t)p2, phi = (uint32_t)(p2 >> 32);
                    float e0 = __int_as_float(plo + (tlo << 23));
                    float e1 = __int_as_float(phi + (thi << 23));
                    acc[mi][ni][2 * h2] = e0;
                    acc[mi][ni][2 * h2 + 1] = e1;
                    s2 = add2(s2, pack2(e0, e1));
                }
                float slo, shi;
                unpack2(s2, slo, shi);
                float s = slo + shi;
                s += __shfl_xor_sync(0xffffffffu, s, 1);
                s += __shfl_xor_sync(0xffffffffu, s, 2);
                if (qd == 0) rs[(wm * 64 + mi * 16 + g + 8 * h2) * 4 + wn] = s;
            }
        __syncthreads();  // (c)

        // ---- W = e * attn_s/rowsum : write attn_w + split to bf16 hi/lo smem ----
#pragma unroll
        for (int mi = 0; mi < 4; mi++)
#pragma unroll
            for (int h2 = 0; h2 < 2; h2++) {
                int r = wm * 64 + mi * 16 + g + 8 * h2;
                float4 rv = *(float4*)(rs + r * 4);
                float tot = (rv.x + rv.y) + (rv.z + rv.w);
                float coef = __fdividef(sAs[r * 32 + nb], tot);
                ull coef2 = pack2(coef, coef);
                float* awp = attnw + ((size_t)((b * HH + hd) * LQ + l0 + r)) * (NBLK * NTOK) +
                             nb * NTOK + wn * 32 + qd * 2;
                char* whp = sm + OFF_WH + r * (WSTR * 2) + (wn * 32 + qd * 2) * 2;
#pragma unroll
                for (int ni = 0; ni < 4; ni++) {
                    ull e2 = pack2(acc[mi][ni][2 * h2], acc[mi][ni][2 * h2 + 1]);
                    ull w2 = mul2(e2, coef2);
                    if (write_attn) *(ull*)(awp + ni * 8) = w2;
                    float w0, w1;
                    unpack2(w2, w0, w1);
                    uint32_t hb;
                    asm("cvt.rn.bf16x2.f32 %0, %1, %2;" : "=r"(hb) : "f"(w1), "f"(w0));
                    float hf0 = __int_as_float(hb << 16);
                    float hf1 = __int_as_float(hb & 0xffff0000u);
                    ull lo2 = fma2(pack2(hf0, hf1), NEG1_2, w2);
                    float q0, q1;
                    unpack2(lo2, q0, q1);
                    uint32_t lb;
                    asm("cvt.rn.bf16x2.f32 %0, %1, %2;" : "=r"(lb) : "f"(q1), "f"(q0));
                    *(uint32_t*)(whp + ni * 16) = hb;
                    *(uint32_t*)(whp + (OFF_WL - OFF_WH) + ni * 16) = lb;
                }
            }
        __syncthreads();  // (d)

        // ---- GEMM2: out(warp m16 x n64) += W @ V, 3 bf16 products ----
#pragma unroll
        for (int ks = 0; ks < 8; ks++) {
            uint32_t Ah4[4], Al4[4];
            ldsm4(Ah4, aW + ks * 32);
            ldsm4(Al4, aW + (OFF_WL - OFF_WH) + ks * 32);
            uint32_t Bh2[8][2], Bl2[8][2];
#pragma unroll
            for (int ni = 0; ni < 8; ni++) {
                ldsm2t(Bh2[ni], bV + ks * (16 * QSTR * 2) + ni * 16);
                ldsm2t(Bl2[ni], bV + (OFF_VL - OFF_VH) + ks * (16 * QSTR * 2) + ni * 16);
            }
#pragma unroll
            for (int ni = 0; ni < 8; ni++) {
                mma16816(acc2[ni], Ah4, Bh2[ni]);
                mma16816(acc2[ni], Ah4, Bl2[ni]);
                mma16816(acc2[ni], Al4, Bh2[ni]);
            }
        }
    }

    // ---- store out [b][l][hd*64+d] ----
#pragma unroll
    for (int h2 = 0; h2 < 2; h2++) {
        int r = wid * 16 + g + 8 * h2;
        float* op = out + ((size_t)(b * LQ + l0 + r)) * (HH * DH) + hd * DH + qd * 2;
#pragma unroll
        for (int ni = 0; ni < 8; ni++) {
            float2 pv;
            pv.x = acc2[ni][2 * h2];
            pv.y = acc2[ni][2 * h2 + 1];
            *(float2*)(op + ni * 8) = pv;
        }
    }
}

extern "C" void kernel_launch(void* const* d_in, const int* in_sizes, int n_in,
                              void* d_out, int out_size) {
    (void)in_sizes; (void)n_in;
    const float* q = (const float*)d_in[0];
    const float* k = (const float*)d_in[1];
    const float* v = (const float*)d_in[2];
    const float* a = (const float*)d_in[3];
    float* out = (float*)d_out;

    int write_attn = ((size_t)out_size >= OUT_ELEMS + ATTN_ELEMS) ? 1 : 0;
    float* attnw = out + OUT_ELEMS;

    cudaFuncSetAttribute(attn_mma_kernel,
                         cudaFuncAttributeMaxDynamicSharedMemorySize, SMEM_BYTES);

    dim3 grid(BB * HH * (LQ / MT));  // 128
    attn_mma_kernel<<<grid, THREADS, SMEM_BYTES>>>(q, k, v, a, out, attnw, write_attn);
}

// round 7
// speedup vs baseline: 5.2986x; 1.3814x over previous
#include <cuda_runtime.h>
#include <cuda_bf16.h>
#include <cstdint>

#define BB 4
#define HH 8
#define LQ 512
#define NBLK 32
#define NTOK 128
#define DH 64
#define MT 128
#define THREADS 256

#define OUT_ELEMS  (BB * LQ * HH * DH)
#define ATTN_ELEMS ((size_t)BB * HH * LQ * NBLK * NTOK)

#define QSTR 72   // bf16 elements per row (64 + 8 pad)

// smem byte offsets
#define OFF_QH 0
#define OFF_QL (OFF_QH + 128 * QSTR * 2)   // 18432 each
#define OFF_KH (OFF_QL + 128 * QSTR * 2)
#define OFF_KL (OFF_KH + 128 * QSTR * 2)
#define OFF_VH (OFF_KL + 128 * QSTR * 2)
#define OFF_VL (OFF_VH + 128 * QSTR * 2)
#define OFF_RS (OFF_VL + 128 * QSTR * 2)   // 128*2 f32 rowsums
#define OFF_STG (OFF_RS + 1024)            // 64KB raw K/V stage
#define SMEM_BYTES (OFF_STG + 65536)       // 177152

#define RED_STR 66  // f32 stride for final reduction scratch (conflict-free)

typedef unsigned long long ull;

__device__ __forceinline__ uint32_t s2u(const void* p) {
    uint32_t a;
    asm("{ .reg .u64 t; cvta.to.shared.u64 t, %1; cvt.u32.u64 %0, t; }" : "=r"(a) : "l"(p));
    return a;
}
__device__ __forceinline__ ull pack2(float x, float y) {
    ull r; asm("mov.b64 %0, {%1,%2};" : "=l"(r) : "f"(x), "f"(y)); return r;
}
__device__ __forceinline__ void unpack2(ull v, float& x, float& y) {
    asm("mov.b64 {%0,%1}, %2;" : "=f"(x), "=f"(y) : "l"(v));
}
__device__ __forceinline__ ull add2(ull a, ull b) {
    ull d; asm("add.rn.f32x2 %0, %1, %2;" : "=l"(d) : "l"(a), "l"(b)); return d;
}
__device__ __forceinline__ ull mul2(ull a, ull b) {
    ull d; asm("mul.rn.f32x2 %0, %1, %2;" : "=l"(d) : "l"(a), "l"(b)); return d;
}
__device__ __forceinline__ ull fma2(ull a, ull b, ull c) {
    ull d; asm("fma.rn.f32x2 %0, %1, %2, %3;" : "=l"(d) : "l"(a), "l"(b), "l"(c)); return d;
}
__device__ __forceinline__ void ldsm4(uint32_t* r, uint32_t a) {
    asm volatile("ldmatrix.sync.aligned.m8n8.x4.shared.b16 {%0,%1,%2,%3}, [%4];"
                 : "=r"(r[0]), "=r"(r[1]), "=r"(r[2]), "=r"(r[3]) : "r"(a));
}
__device__ __forceinline__ void ldsm2(uint32_t* r, uint32_t a) {
    asm volatile("ldmatrix.sync.aligned.m8n8.x2.shared.b16 {%0,%1}, [%2];"
                 : "=r"(r[0]), "=r"(r[1]) : "r"(a));
}
__device__ __forceinline__ void ldsm2t(uint32_t* r, uint32_t a) {
    asm volatile("ldmatrix.sync.aligned.m8n8.x2.trans.shared.b16 {%0,%1}, [%2];"
                 : "=r"(r[0]), "=r"(r[1]) : "r"(a));
}
__device__ __forceinline__ void mma16816(float* c, const uint32_t* a, const uint32_t* b) {
    asm volatile(
        "mma.sync.aligned.m16n8k16.row.col.f32.bf16.bf16.f32 "
        "{%0,%1,%2,%3}, {%4,%5,%6,%7}, {%8,%9}, {%0,%1,%2,%3};"
        : "+f"(c[0]), "+f"(c[1]), "+f"(c[2]), "+f"(c[3])
        : "r"(a[0]), "r"(a[1]), "r"(a[2]), "r"(a[3]), "r"(b[0]), "r"(b[1]));
}
__device__ __forceinline__ void cpa16(uint32_t dst, const void* src) {
    asm volatile("cp.async.cg.shared.global [%0], [%1], 16;" :: "r"(dst), "l"(src));
}
#define CP_COMMIT() asm volatile("cp.async.commit_group;" ::: "memory")
#define CP_WAIT0()  asm volatile("cp.async.wait_group 0;" ::: "memory")
__device__ __forceinline__ void barpair(int id) {
    asm volatile("bar.sync %0, 64;" :: "r"(id) : "memory");
}

// split one fp32 float4 into bf16 hi/lo, store 8B each
__device__ __forceinline__ void split_store(float4 v, char* base_hi, char* base_lo) {
    __nv_bfloat162 h0 = __floats2bfloat162_rn(v.x, v.y);
    __nv_bfloat162 h1 = __floats2bfloat162_rn(v.z, v.w);
    float lx = v.x - __bfloat162float(h0.x);
    float ly = v.y - __bfloat162float(h0.y);
    float lz = v.z - __bfloat162float(h1.x);
    float lw = v.w - __bfloat162float(h1.y);
    __nv_bfloat162 e0 = __floats2bfloat162_rn(lx, ly);
    __nv_bfloat162 e1 = __floats2bfloat162_rn(lz, lw);
    uint2 hh; hh.x = *(uint32_t*)&h0; hh.y = *(uint32_t*)&h1;
    uint2 ll; ll.x = *(uint32_t*)&e0; ll.y = *(uint32_t*)&e1;
    *(uint2*)base_hi = hh;
    *(uint2*)base_lo = ll;
}

__global__ __launch_bounds__(THREADS, 1)
void attn_mma_kernel(const float* __restrict__ qg, const float* __restrict__ kg,
                     const float* __restrict__ vg, const float* __restrict__ ag,
                     float* __restrict__ out, float* __restrict__ attnw, int write_attn) {
    extern __shared__ __align__(16) char sm[];
    const uint32_t sb = s2u(sm);
    const int tid = threadIdx.x, lane = tid & 31, wid = tid >> 5;
    const int wm = wid >> 1, wn = wid & 1;
    const int g = lane >> 2, qd = lane & 3;
    const int bx = blockIdx.x;
    const int qt = bx & 3, hd = (bx >> 2) & 7, b = bx >> 5;
    const int l0 = qt * MT;

    const size_t kvstride = (size_t)HH * NTOK * DH;  // floats between blocks
    const size_t kvoff0 = ((size_t)(b * NBLK) * HH + hd) * (NTOK * DH);

    // ---- prefetch K/V block 0 into stage ----
    {
        const float4* kg4 = (const float4*)(kg + kvoff0);
        const float4* vg4 = (const float4*)(vg + kvoff0);
#pragma unroll
        for (int i = 0; i < 8; i++) {
            int idx = tid + i * THREADS;
            cpa16(sb + OFF_STG + idx * 16, kg4 + idx);
            cpa16(sb + OFF_STG + 32768 + idx * 16, vg4 + idx);
        }
        CP_COMMIT();
    }

    // ---- Q load + split (scale = 1/8 * log2e folded) ----
    {
        const float SC = 0.125f * 1.4426950408889634f;
        const float4* qg4 = (const float4*)(qg + (size_t)((b * HH + hd) * LQ + l0) * DH);
#pragma unroll
        for (int i = 0; i < 8; i++) {
            int idx = tid + i * THREADS;
            int row = idx >> 4, c4 = idx & 15;
            float4 v = qg4[idx];
            v.x *= SC; v.y *= SC; v.z *= SC; v.w *= SC;
            char* base = sm + row * (QSTR * 2) + c4 * 8;
            split_store(v, base + OFF_QH, base + OFF_QL);
        }
    }

    // ldmatrix base addresses
    const uint32_t aQ = sb + OFF_QH +
        (uint32_t)(((wm * 32 + (lane & 15)) * QSTR + (lane >> 4) * 8) * 2);
    const uint32_t bK = sb + OFF_KH +
        (uint32_t)(((wn * 64 + (lane & 7)) * QSTR + ((lane >> 3) & 1) * 8) * 2);
    const uint32_t bV = sb + OFF_VH + (uint32_t)(((wn * 64 + (lane & 15)) * QSTR) * 2);

    float* rs = (float*)(sm + OFF_RS);
    const float* asbase = ag + (size_t)((b * HH + hd) * LQ + l0 + wm * 32 + g) * NBLK;
    float* awbase = attnw + (size_t)((b * HH + hd) * LQ + l0 + wm * 32 + g) * (NBLK * NTOK)
                    + wn * 64 + 2 * qd;

    float acc2[2][8][4];
#pragma unroll
    for (int mi = 0; mi < 2; mi++)
#pragma unroll
        for (int ni = 0; ni < 8; ni++)
#pragma unroll
            for (int j = 0; j < 4; j++) acc2[mi][ni][j] = 0.f;

    // exp2 constants
    const ull MAGIC2 = 0x4B4000004B400000ULL;
    const ull NMAGIC2 = 0xCB400000CB400000ULL;
    const ull NEG1_2 = 0xBF800000BF800000ULL;
    const ull ONE2 = 0x3F8000003F800000ULL;
    const ull C5 = pack2(0.0013333558f, 0.0013333558f);
    const ull C4 = pack2(0.0096181291f, 0.0096181291f);
    const ull C3 = pack2(0.0555041087f, 0.0555041087f);
    const ull C2 = pack2(0.2402265070f, 0.2402265070f);
    const ull C1 = pack2(0.6931471806f, 0.6931471806f);

    for (int nb = 0; nb < NBLK; nb++) {
        CP_WAIT0();
        __syncthreads();  // stage(nb) visible; GEMM2(nb-1) done with K/V tiles

        // ---- split stage -> bf16 hi/lo tiles ----
        {
            const float4* stK = (const float4*)(sm + OFF_STG);
            const float4* stV = (const float4*)(sm + OFF_STG + 32768);
#pragma unroll
            for (int i = 0; i < 8; i++) {
                int idx = tid + i * THREADS;
                int row = idx >> 4, c4 = idx & 15;
                char* base = sm + row * (QSTR * 2) + c4 * 8;
                split_store(stK[idx], base + OFF_KH, base + OFF_KL);
                split_store(stV[idx], base + OFF_VH, base + OFF_VL);
            }
        }
        __syncthreads();  // tiles ready; stage fully consumed

        // ---- prefetch next block ----
        if (nb + 1 < NBLK) {
            const float4* kg4 = (const float4*)(kg + kvoff0 + (size_t)(nb + 1) * kvstride);
            const float4* vg4 = (const float4*)(vg + kvoff0 + (size_t)(nb + 1) * kvstride);
#pragma unroll
            for (int i = 0; i < 8; i++) {
                int idx = tid + i * THREADS;
                cpa16(sb + OFF_STG + idx * 16, kg4 + idx);
                cpa16(sb + OFF_STG + 32768 + idx * 16, vg4 + idx);
            }
        }
        CP_COMMIT();

        // attn_s values for this thread's 4 rows (L1-resident line per row)
        float asv[2][2];
#pragma unroll
        for (int mi = 0; mi < 2; mi++)
#pragma unroll
            for (int h2 = 0; h2 < 2; h2++)
                asv[mi][h2] = __ldg(asbase + (mi * 16 + 8 * h2) * NBLK + nb);

        // ---- GEMM1: S(warp m32 x t64) = Q @ K^T, 3 bf16 products ----
        float acc[2][8][4];
#pragma unroll
        for (int mi = 0; mi < 2; mi++)
#pragma unroll
            for (int ni = 0; ni < 8; ni++)
#pragma unroll
                for (int j = 0; j < 4; j++) acc[mi][ni][j] = 0.f;

#pragma unroll
        for (int ks = 0; ks < 4; ks++) {
            uint32_t Ah[2][4], Al[2][4], Bh[8][2], Bl[8][2];
#pragma unroll
            for (int mi = 0; mi < 2; mi++) {
                ldsm4(Ah[mi], aQ + mi * (16 * QSTR * 2) + ks * 32);
                ldsm4(Al[mi], aQ + (OFF_QL - OFF_QH) + mi * (16 * QSTR * 2) + ks * 32);
            }
#pragma unroll
            for (int ni = 0; ni < 8; ni++) {
                ldsm2(Bh[ni], bK + ni * (8 * QSTR * 2) + ks * 32);
                ldsm2(Bl[ni], bK + (OFF_KL - OFF_KH) + ni * (8 * QSTR * 2) + ks * 32);
            }
#pragma unroll
            for (int mi = 0; mi < 2; mi++)
#pragma unroll
                for (int ni = 0; ni < 8; ni++) {
                    mma16816(acc[mi][ni], Ah[mi], Bh[ni]);
                    mma16816(acc[mi][ni], Ah[mi], Bl[ni]);
                    mma16816(acc[mi][ni], Al[mi], Bh[ni]);
                }
        }

        // ---- softmax: e = 2^S, partial rowsums over this warp's t64 ----
        float coef[2][2];
#pragma unroll
        for (int mi = 0; mi < 2; mi++)
#pragma unroll
            for (int h2 = 0; h2 < 2; h2++) {
                ull s2 = 0ULL;
#pragma unroll
                for (int ni = 0; ni < 8; ni++) {
                    ull y2 = pack2(acc[mi][ni][2 * h2], acc[mi][ni][2 * h2 + 1]);
                    ull t2 = add2(y2, MAGIC2);
                    ull u2 = add2(t2, NMAGIC2);
                    ull f2 = fma2(u2, NEG1_2, y2);
                    ull p2 = fma2(C5, f2, C4);
                    p2 = fma2(p2, f2, C3);
                    p2 = fma2(p2, f2, C2);
                    p2 = fma2(p2, f2, C1);
                    p2 = fma2(p2, f2, ONE2);
                    uint32_t tlo = (uint32_t)t2, thi = (uint32_t)(t2 >> 32);
                    uint32_t plo = (uint32_t)p2, phi = (uint32_t)(p2 >> 32);
                    float e0 = __int_as_float(plo + (tlo << 23));
                    float e1 = __int_as_float(phi + (thi << 23));
                    acc[mi][ni][2 * h2] = e0;
                    acc[mi][ni][2 * h2 + 1] = e1;
                    s2 = add2(s2, pack2(e0, e1));
                }
                float slo, shi;
                unpack2(s2, slo, shi);
                float s = slo + shi;
                s += __shfl_xor_sync(0xffffffffu, s, 1);
                s += __shfl_xor_sync(0xffffffffu, s, 2);
                if (qd == 0) rs[(wm * 32 + mi * 16 + g + 8 * h2) * 2 + wn] = s;
            }
        barpair(1 + wm);  // exchange rowsums within the (wn=0, wn=1) pair
#pragma unroll
        for (int mi = 0; mi < 2; mi++)
#pragma unroll
            for (int h2 = 0; h2 < 2; h2++) {
                int r = wm * 32 + mi * 16 + g + 8 * h2;
                float tot = rs[r * 2] + rs[r * 2 + 1];
                coef[mi][h2] = __fdividef(asv[mi][h2], tot);
            }

        // ---- GEMM2 (W in registers): out += W @ V, attn_w written en route ----
        float* awp = awbase + nb * NTOK;
#pragma unroll
        for (int kt = 0; kt < 4; kt++) {
            uint32_t Bh2[8][2], Bl2[8][2];
#pragma unroll
            for (int ni = 0; ni < 8; ni++) {
                ldsm2t(Bh2[ni], bV + kt * (16 * QSTR * 2) + ni * 16);
                ldsm2t(Bl2[ni], bV + (OFF_VL - OFF_VH) + kt * (16 * QSTR * 2) + ni * 16);
            }
            uint32_t Awh[2][4], Awl[2][4];
#pragma unroll
            for (int mi = 0; mi < 2; mi++) {
                ull c2h0 = pack2(coef[mi][0], coef[mi][0]);
                ull c2h1 = pack2(coef[mi][1], coef[mi][1]);
#pragma unroll
                for (int half = 0; half < 2; half++) {   // half 0 -> tile 2kt, 1 -> 2kt+1
                    int ni = 2 * kt + half;
                    ull w0 = mul2(pack2(acc[mi][ni][0], acc[mi][ni][1]), c2h0); // row g
                    ull w1 = mul2(pack2(acc[mi][ni][2], acc[mi][ni][3]), c2h1); // row g+8
                    if (write_attn) {
                        *(ull*)(awp + (mi * 16) * (NBLK * NTOK) + ni * 8) = w0;
                        *(ull*)(awp + (mi * 16 + 8) * (NBLK * NTOK) + ni * 8) = w1;
                    }
                    float x0, x1, y0, y1;
                    unpack2(w0, x0, x1);
                    unpack2(w1, y0, y1);
                    uint32_t hb0, hb1;
                    asm("cvt.rn.bf16x2.f32 %0, %1, %2;" : "=r"(hb0) : "f"(x1), "f"(x0));
                    asm("cvt.rn.bf16x2.f32 %0, %1, %2;" : "=r"(hb1) : "f"(y1), "f"(y0));
                    Awh[mi][half * 2] = hb0;      // a0 / a2
                    Awh[mi][half * 2 + 1] = hb1;  // a1 / a3
                    ull hf0 = pack2(__int_as_float(hb0 << 16), __int_as_float(hb0 & 0xffff0000u));
                    ull hf1 = pack2(__int_as_float(hb1 << 16), __int_as_float(hb1 & 0xffff0000u));
                    ull l0v = fma2(hf0, NEG1_2, w0);
                    ull l1v = fma2(hf1, NEG1_2, w1);
                    float q0, q1, q2, q3;
                    unpack2(l0v, q0, q1);
                    unpack2(l1v, q2, q3);
                    uint32_t lb0, lb1;
                    asm("cvt.rn.bf16x2.f32 %0, %1, %2;" : "=r"(lb0) : "f"(q1), "f"(q0));
                    asm("cvt.rn.bf16x2.f32 %0, %1, %2;" : "=r"(lb1) : "f"(q3), "f"(q2));
                    Awl[mi][half * 2] = lb0;
                    Awl[mi][half * 2 + 1] = lb1;
                }
            }
#pragma unroll
            for (int mi = 0; mi < 2; mi++)
#pragma unroll
                for (int ni = 0; ni < 8; ni++) {
                    mma16816(acc2[mi][ni], Awh[mi], Bh2[ni]);
                    mma16816(acc2[mi][ni], Awh[mi], Bl2[ni]);
                    mma16816(acc2[mi][ni], Awl[mi], Bh2[ni]);
                }
        }
    }

    // ---- pair reduction (wn=0 + wn=1) via stage scratch, then store out ----
    float* red = (float*)(sm + OFF_STG) + wm * (32 * RED_STR);
    if (wn == 1) {
#pragma unroll
        for (int mi = 0; mi < 2; mi++)
#pragma unroll
            for (int h2 = 0; h2 < 2; h2++)
#pragma unroll
                for (int ni = 0; ni < 8; ni++) {
                    int row = mi * 16 + g + 8 * h2;
                    float2 pv;
                    pv.x = acc2[mi][ni][2 * h2];
                    pv.y = acc2[mi][ni][2 * h2 + 1];
                    *(float2*)(red + row * RED_STR + ni * 8 + 2 * qd) = pv;
                }
    }
    barpair(1 + wm);
    if (wn == 0) {
#pragma unroll
        for (int mi = 0; mi < 2; mi++)
#pragma unroll
            for (int h2 = 0; h2 < 2; h2++) {
                int row = mi * 16 + g + 8 * h2;
                float* op = out + (size_t)(b * LQ + l0 + wm * 32 + row) * (HH * DH) + hd * DH;
#pragma unroll
                for (int ni = 0; ni < 8; ni++) {
                    float2 o = *(float2*)(red + row * RED_STR + ni * 8 + 2 * qd);
                    float2 pv;
                    pv.x = acc2[mi][ni][2 * h2] + o.x;
                    pv.y = acc2[mi][ni][2 * h2 + 1] + o.y;
                    *(float2*)(op + ni * 8 + 2 * qd) = pv;
                }
            }
    }
}

extern "C" void kernel_launch(void* const* d_in, const int* in_sizes, int n_in,
                              void* d_out, int out_size) {
    (void)in_sizes; (void)n_in;
    const float* q = (const float*)d_in[0];
    const float* k = (const float*)d_in[1];
    const float* v = (const float*)d_in[2];
    const float* a = (const float*)d_in[3];
    float* out = (float*)d_out;

    int write_attn = ((size_t)out_size >= OUT_ELEMS + ATTN_ELEMS) ? 1 : 0;
    float* attnw = out + OUT_ELEMS;

    cudaFuncSetAttribute(attn_mma_kernel,
                         cudaFuncAttributeMaxDynamicSharedMemorySize, SMEM_BYTES);

    dim3 grid(BB * HH * (LQ / MT));  // 128
    attn_mma_kernel<<<grid, THREADS, SMEM_BYTES>>>(q, k, v, a, out, attnw, write_attn);
}